// round 6
// baseline (speedup 1.0000x reference)
#include <cuda_runtime.h>
#include <math.h>

#define N_NODES 10000
#define N_EDGES 320000
#define IN_DIM  512
#define CH      128

// ---------------- device scratch (no allocations allowed) ----------------
__device__ __align__(16) float g_h[N_NODES * CH];    // normalized h
__device__ __align__(16) float g_xw[N_NODES * CH];   // h @ Wg^T
__device__ __align__(16) float g_z1[N_NODES * CH];   // GCN output
__device__ float g_y0[N_NODES];
__device__ float g_y1[N_NODES];
__device__ float g_z20[N_NODES];
__device__ float g_dinv[N_NODES];
__device__ int   g_deg[N_NODES];
__device__ int   g_cursor[N_NODES];
__device__ int   g_off[N_NODES];
__device__ int   g_bucket[N_EDGES];
__device__ int   g_is64;

// edge_index may be int64 or int32 depending on JAX x64 config; branch on probe.
__device__ __forceinline__ int eload(const void* p, long long pos) {
    if (g_is64) return (int)((const long long*)p)[pos];
    return ((const int*)p)[pos];
}

// ---------------- K0: zero counters + dtype probe ----------------
__global__ void k0_init(const void* __restrict__ ei) {
    int gid = blockIdx.x * blockDim.x + threadIdx.x;
    int stride = gridDim.x * blockDim.x;
    for (int i = gid; i < N_NODES; i += stride) {
        g_deg[i] = 0; g_cursor[i] = 0; g_y0[i] = 0.f; g_y1[i] = 0.f;
    }
    if (blockIdx.x == 0) {
        __shared__ int nz;
        if (threadIdx.x == 0) nz = 0;
        __syncthreads();
        if (threadIdx.x < 128) {
            // int64 storage (ids < 2^31): every odd 32-bit word is 0.
            // int32 storage: odd words are random node ids; 128 all-zero ~ impossible.
            int v = ((const int*)ei)[2 * threadIdx.x + 1];
            if (v != 0) atomicOr(&nz, 1);
        }
        __syncthreads();
        if (threadIdx.x == 0) g_is64 = (nz == 0) ? 1 : 0;
    }
}

// ---------------- shared GEMM tile: out[m][n] = A[m][:]·W[n][:] (+bias, +l2norm) ----
// BM=64, BN=128(full), BK=32; 256 threads, 4x8 register tile per thread.
template <int K, bool BIAS, bool NORM>
__device__ __forceinline__ void gemm_tile(
    const float* __restrict__ A,    // [M][K] row-major
    const float* __restrict__ W,    // [128][K] row-major
    const float* __restrict__ bias, // [128] or nullptr
    float* __restrict__ out,        // [M][128]
    int m0, int M, float* sm)
{
    float* As = sm;           // [32][64]   (k-major, transposed)
    float* Bs = sm + 2048;    // [32][132]  (padded)
    const int tid = threadIdx.x;
    const int tx = tid & 15;        // n-group: cols tx*8..tx*8+7
    const int ty = tid >> 4;        // m-group: rows ty*4..ty*4+3

    float acc[4][8];
#pragma unroll
    for (int i = 0; i < 4; i++)
#pragma unroll
        for (int j = 0; j < 8; j++) acc[i][j] = 0.f;

    for (int k0 = 0; k0 < K; k0 += 32) {
        // load A tile (64 rows x 32 k), store transposed As[kk][m]
        {
            int m = tid >> 2;
            int q0 = tid & 3;
#pragma unroll
            for (int h = 0; h < 2; h++) {
                int q = q0 + h * 4; // float4 index 0..7 within the 32-k chunk
                float4 v = make_float4(0.f, 0.f, 0.f, 0.f);
                if (m0 + m < M)
                    v = *(const float4*)&A[(size_t)(m0 + m) * K + k0 + q * 4];
                As[(q * 4 + 0) * 64 + m] = v.x;
                As[(q * 4 + 1) * 64 + m] = v.y;
                As[(q * 4 + 2) * 64 + m] = v.z;
                As[(q * 4 + 3) * 64 + m] = v.w;
            }
        }
        // load W tile (128 n x 32 k), store transposed Bs[kk][n]
        {
            int n = tid >> 1;
            int half = tid & 1;
#pragma unroll
            for (int j = 0; j < 4; j++) {
                int q = half * 4 + j;
                float4 w = *(const float4*)&W[(size_t)n * K + k0 + q * 4];
                Bs[(q * 4 + 0) * 132 + n] = w.x;
                Bs[(q * 4 + 1) * 132 + n] = w.y;
                Bs[(q * 4 + 2) * 132 + n] = w.z;
                Bs[(q * 4 + 3) * 132 + n] = w.w;
            }
        }
        __syncthreads();
#pragma unroll
        for (int kk = 0; kk < 32; kk++) {
            float4 a  = *(const float4*)&As[kk * 64 + ty * 4];
            float4 b0 = *(const float4*)&Bs[kk * 132 + tx * 8];
            float4 b1 = *(const float4*)&Bs[kk * 132 + tx * 8 + 4];
            float av[4] = {a.x, a.y, a.z, a.w};
            float bv[8] = {b0.x, b0.y, b0.z, b0.w, b1.x, b1.y, b1.z, b1.w};
#pragma unroll
            for (int i = 0; i < 4; i++)
#pragma unroll
                for (int j = 0; j < 8; j++) acc[i][j] += av[i] * bv[j];
        }
        __syncthreads();
    }

    // epilogue via smem staging (reuses As/Bs region): sOut[64][129] + sNorm[64]
    float* sOut = sm;
    float* sNorm = sm + 64 * 129;
#pragma unroll
    for (int i = 0; i < 4; i++) {
        int row = ty * 4 + i;
#pragma unroll
        for (int j = 0; j < 8; j++) {
            float v = acc[i][j];
            if (BIAS) v += bias[tx * 8 + j];
            sOut[row * 129 + tx * 8 + j] = v;
        }
    }
    __syncthreads();
    if (NORM) {
        if (tid < 64) {
            float ss = 0.f;
#pragma unroll 4
            for (int c = 0; c < 128; c++) {
                float u = sOut[tid * 129 + c];
                ss += u * u;
            }
            sNorm[tid] = 1.8f / fmaxf(sqrtf(ss), 1e-12f);
        }
        __syncthreads();
    }
#pragma unroll
    for (int i = 0; i < 32; i++) {
        int e = i * 256 + tid;          // coalesced: consecutive tid -> consecutive col
        int row = e >> 7, col = e & 127;
        if (m0 + row < M) {
            float v = sOut[row * 129 + col];
            if (NORM) v *= sNorm[row];
            out[(size_t)(m0 + row) * 128 + col] = v;
        }
    }
}

// ---------------- K1 fused: [x2 GEMV tiles | h GEMM | degree count] ----------------
#define NB_GEMV 395   // 79 row-tiles (128 rows) x 5 col-tiles (2048 cols)
#define NB_GEMM1 157  // ceil(10000/64)
#define NB_DEG 96

__global__ __launch_bounds__(256) void k1_fused(
    const float* __restrict__ x, const float* __restrict__ x2,
    const float* __restrict__ W2, const float* __restrict__ b2,
    const float* __restrict__ W22, const void* __restrict__ ei)
{
    extern __shared__ float sm[];
    int bid = blockIdx.x;

    if (bid < NB_GEMV) {
        // ---- x2 @ W22^T partial dot over a (128-row x 2048-col) tile ----
        int rt = bid / 5, ct = bid % 5;
        int c0 = ct * 2048;
        int clen = min(2048, N_NODES - c0);   // 2048 or 1808 (mult of 16)
        float* w0 = sm;
        float* w1 = sm + 2048;
        for (int i = threadIdx.x; i < 2048; i += 256) {
            w0[i] = (i < clen) ? W22[c0 + i] : 0.f;
            w1[i] = (i < clen) ? W22[N_NODES + c0 + i] : 0.f;
        }
        __syncthreads();
        int lane = threadIdx.x & 31, wid = threadIdx.x >> 5;
        int nvec = clen >> 2;
        for (int rr = wid; rr < 128; rr += 8) {
            int row = rt * 128 + rr;
            if (row >= N_NODES) break;
            const float4* xr = (const float4*)(x2 + (size_t)row * N_NODES + c0);
            float a0 = 0.f, a1 = 0.f;
            for (int it = lane; it < nvec; it += 32) {
                float4 v = xr[it];
                float4 u0 = *(const float4*)&w0[it * 4];
                float4 u1 = *(const float4*)&w1[it * 4];
                a0 += v.x * u0.x + v.y * u0.y + v.z * u0.z + v.w * u0.w;
                a1 += v.x * u1.x + v.y * u1.y + v.z * u1.z + v.w * u1.w;
            }
#pragma unroll
            for (int o = 16; o; o >>= 1) {
                a0 += __shfl_xor_sync(0xffffffffu, a0, o);
                a1 += __shfl_xor_sync(0xffffffffu, a1, o);
            }
            if (lane == 0) {
                atomicAdd(&g_y0[row], a0);
                atomicAdd(&g_y1[row], a1);
            }
        }
    } else if (bid < NB_GEMV + NB_GEMM1) {
        // ---- h = l2norm(x @ W2^T + b2) * 1.8 ----
        gemm_tile<IN_DIM, true, true>(x, W2, b2, g_h, (bid - NB_GEMV) * 64, N_NODES, sm);
    } else {
        // ---- in-degree counting (edge targets) ----
        int lb = bid - NB_GEMV - NB_GEMM1;
        int stride = NB_DEG * 256;
        for (int e = lb * 256 + threadIdx.x; e < N_EDGES; e += stride) {
            int c = eload(ei, (long long)N_EDGES + e);
            atomicAdd(&g_deg[c], 1);
        }
    }
}

// ---------------- K2 fused: [xw GEMM | dinv + z2-normalize | degree prefix scan] ----
#define NB_GEMM2 157
__global__ __launch_bounds__(256) void k2_fused(const float* __restrict__ Wg)
{
    extern __shared__ float sm[];
    int bid = blockIdx.x;
    if (bid < NB_GEMM2) {
        gemm_tile<CH, false, false>(g_h, Wg, nullptr, g_xw, bid * 64, N_NODES, sm);
    } else if (bid < NB_GEMM2 + 8) {
        int lb = bid - NB_GEMM2;
        for (int i = lb * 256 + threadIdx.x; i < N_NODES; i += 8 * 256) {
            g_dinv[i] = rsqrtf((float)(g_deg[i] + 1));   // +1 self-loop
            float y0 = g_y0[i], y1 = g_y1[i];
            float n = sqrtf(y0 * y0 + y1 * y1);
            g_z20[i] = 0.8f * y0 / fmaxf(n, 1e-12f);
        }
    } else {
        // single-block exclusive scan of g_deg -> g_off
        int* ssum = (int*)sm;
        const int CHUNK = 40;                 // 256*40 = 10240 >= 10000
        int t = threadIdx.x;
        int base = t * CHUNK;
        int s = 0;
        for (int j = 0; j < CHUNK; j++) {
            int idx = base + j;
            if (idx < N_NODES) s += g_deg[idx];
        }
        ssum[t] = s;
        __syncthreads();
        for (int off = 1; off < 256; off <<= 1) {
            int u = (t >= off) ? ssum[t - off] : 0;
            __syncthreads();
            ssum[t] += u;
            __syncthreads();
        }
        int run = ssum[t] - s;  // exclusive
        for (int j = 0; j < CHUNK; j++) {
            int idx = base + j;
            if (idx < N_NODES) {
                g_off[idx] = run;
                run += g_deg[idx];
            }
        }
    }
}

// ---------------- K3: bin edge sources into per-target CSR buckets ----------------
__global__ void k3_fill(const void* __restrict__ ei)
{
    int stride = gridDim.x * blockDim.x;
    for (int e = blockIdx.x * blockDim.x + threadIdx.x; e < N_EDGES; e += stride) {
        int r = eload(ei, e);
        int c = eload(ei, (long long)N_EDGES + e);
        int pos = atomicAdd(&g_cursor[c], 1);
        g_bucket[g_off[c] + pos] = r;
    }
}

// ---------------- K4: warp-per-node pull aggregation (GCN) ----------------
__global__ __launch_bounds__(256) void k4_agg(const float* __restrict__ bg)
{
    int node = blockIdx.x * 8 + (threadIdx.x >> 5);
    if (node >= N_NODES) return;
    int lane = threadIdx.x & 31;   // lane handles channels lane*4 .. lane*4+3

    float dc = g_dinv[node];
    float4 bgv = ((const float4*)bg)[lane];
    float4 xv = *(const float4*)&g_xw[(size_t)node * CH + lane * 4];
    float sl = dc * dc;            // self-loop norm
    float4 acc;
    acc.x = bgv.x + xv.x * sl;
    acc.y = bgv.y + xv.y * sl;
    acc.z = bgv.z + xv.z * sl;
    acc.w = bgv.w + xv.w * sl;

    int beg = g_off[node];
    int end = beg + g_deg[node];
    for (int j = beg; j < end; j++) {
        int r = g_bucket[j];                          // broadcast load
        float w = g_dinv[r] * dc;
        float4 v = *(const float4*)&g_xw[(size_t)r * CH + lane * 4];
        acc.x += v.x * w; acc.y += v.y * w; acc.z += v.z * w; acc.w += v.w * w;
    }
    *(float4*)&g_z1[(size_t)node * CH + lane * 4] = acc;
}

// ---------------- K5: warp-per-edge decoder ----------------
__global__ __launch_bounds__(256) void k5_edge(const void* __restrict__ ei,
                                               float* __restrict__ out)
{
    int e = blockIdx.x * 8 + (threadIdx.x >> 5);
    if (e >= N_EDGES) return;
    int lane = threadIdx.x & 31;
    int r = eload(ei, e);
    int c = eload(ei, (long long)N_EDGES + e);

    float4 a = *(const float4*)&g_z1[(size_t)r * CH + lane * 4];
    float4 b = *(const float4*)&g_z1[(size_t)c * CH + lane * 4];
    float p = a.x * b.x + a.y * b.y + a.z * b.z + a.w * b.w;
#pragma unroll
    for (int o = 16; o; o >>= 1) p += __shfl_xor_sync(0xffffffffu, p, o);

    if (lane == 0) {
        float vn = g_z20[r] + g_z20[c];
        float sf = 1.f / (1.f + expf(-p));
        float sn = 1.f / (1.f + expf(-vn));
        out[e] = sf * sf + (1.f - sf) * sn;
    }
}

// ---------------- launch ----------------
extern "C" void kernel_launch(void* const* d_in, const int* in_sizes, int n_in,
                              void* d_out, int out_size)
{
    const float* x   = (const float*)d_in[0];
    const float* x2  = (const float*)d_in[1];
    const float* W2  = (const float*)d_in[2];
    const float* b2  = (const float*)d_in[3];
    const float* Wg  = (const float*)d_in[4];
    const float* bg  = (const float*)d_in[5];
    const float* W22 = (const float*)d_in[6];
    const void*  ei  = d_in[7];
    float* out = (float*)d_out;

    const int SMEM = 33536;  // max(As+Bs=25088, sOut+sNorm=33280, GEMV 16KB, scan 1KB)

    k0_init<<<64, 256>>>(ei);
    k1_fused<<<NB_GEMV + NB_GEMM1 + NB_DEG, 256, SMEM>>>(x, x2, W2, b2, W22, ei);
    k2_fused<<<NB_GEMM2 + 8 + 1, 256, SMEM>>>(Wg);
    k3_fill<<<320, 256>>>(ei);
    k4_agg<<<(N_NODES + 7) / 8, 256>>>(bg);
    k5_edge<<<(N_EDGES + 7) / 8, 256>>>(ei, out);
}